// round 13
// baseline (speedup 1.0000x reference)
#include <cuda_runtime.h>
#include <cuda_fp16.h>
#include <cstdint>

// Problem constants
#define BB 32
#define CC 256
#define HH 32
#define WW 32
#define KK 1024
#define NN 1024                      // H*W
#define ZP_BATCH (CC * NN)           // 262144 floats per batch
#define ZQ_SIZE (BB * CC * HH * WW)  // 8388608
#define IDX_SIZE (BB * NN)           // 32768

// ---------------- k_mma smem layout (u32 units) ----------------
// A hi [128 n][132] @ 0 (16896)
// E ring [4 buf][128 k][20] @ 16896 (10240)
// e2s float[1024] @ 27136
#define OFF_AH 0
#define OFF_EB 16896
#define EB_SEG 2560
#define OFF_E2 27136
#define SMEM_U32 28160
#define SMEM_MMA_BYTES (SMEM_U32 * 4)   // 112640

// Device scratch (allocation-free rule: __device__ globals)
__device__ float g_zp[BB * ZP_BATCH];   // contiguous [b][h][w][c] image of z_p
__device__ float g_e2[KK];
__device__ float g_z2[BB * NN];         // view-column norms
__device__ int   g_idx[BB * NN];
__device__ float g_losspart[1024];
__device__ unsigned int g_smax_bits;    // max_k sqrt(e2[k]) as float bits
__device__ int   g_cnt;                 // flagged-pixel count
__device__ int   g_list[BB * NN];       // flagged pixel ids
// pre-split fp16 hi operands
__device__ __align__(16) __half g_eh[KK * CC];          // E hi halves [k][c]
__device__ __align__(16) __half g_zh[BB * NN * CC];     // A hi halves [b][n][c] (view rows)

// ---------- helpers ----------
__device__ __forceinline__ uint32_t smem_u32(const void* p) {
    uint32_t a;
    asm("{ .reg .u64 t; cvta.to.shared.u64 t, %1; cvt.u32.u64 %0, t; }" : "=r"(a) : "l"(p));
    return a;
}
__device__ __forceinline__ void ldsm4(uint32_t* r, uint32_t addr) {
    asm volatile("ldmatrix.sync.aligned.m8n8.x4.shared.b16 {%0,%1,%2,%3}, [%4];"
                 : "=r"(r[0]), "=r"(r[1]), "=r"(r[2]), "=r"(r[3]) : "r"(addr));
}
__device__ __forceinline__ void mma_f16(float* d, const uint32_t* a,
                                        uint32_t b0, uint32_t b1) {
    asm volatile(
        "mma.sync.aligned.m16n8k16.row.col.f32.f16.f16.f32 "
        "{%0,%1,%2,%3}, {%4,%5,%6,%7}, {%8,%9}, {%0,%1,%2,%3};"
        : "+f"(d[0]), "+f"(d[1]), "+f"(d[2]), "+f"(d[3])
        : "r"(a[0]), "r"(a[1]), "r"(a[2]), "r"(a[3]), "r"(b0), "r"(b1));
}
// top-2 update: lexicographic first-k; invariant v2 >= v1
__device__ __forceinline__ void top2_upd(float& v1, int& k1, float& v2, float d, int k) {
    if (d < v1 || (d == v1 && k < k1)) { v2 = v1; v1 = d; k1 = k; }
    else v2 = fminf(v2, d);
}
__device__ __forceinline__ void top2_merge(float& v1, int& k1, float& v2,
                                           float V1, int K1, float V2) {
    if (V1 < v1 || (V1 == v1 && K1 < k1)) { v2 = fminf(v1, V2); v1 = V1; k1 = K1; }
    else v2 = fminf(v2, V1);
}

// ---------- kernel 0: per-launch scalar init ----------
__global__ void k_init() { g_cnt = 0; g_smax_bits = 0u; }

// ---------- kernel 1: e2[k] + pre-split E hi halves + smax ----------
__global__ void k_e2(const float* __restrict__ E) {
    int warp = threadIdx.x >> 5, lane = threadIdx.x & 31;
    int k = blockIdx.x * 8 + warp;
    const float* row = E + k * CC;
    float v[8];
    float s = 0.f;
#pragma unroll
    for (int i = 0; i < 8; i++) { v[i] = row[lane + 32 * i]; s = fmaf(v[i], v[i], s); }
#pragma unroll
    for (int o = 16; o; o >>= 1) s += __shfl_xor_sync(0xFFFFFFFFu, s, o);
    if (lane == 0) {
        g_e2[k] = s;
        atomicMax(&g_smax_bits, __float_as_uint(sqrtf(s)));
    }
#pragma unroll
    for (int i = 0; i < 8; i++)
        g_eh[k * CC + lane + 32 * i] = __float2half_rn(v[i]);
}

// ---------- kernel 2: transpose z -> g_zp, emit A-row hi halves ----------
__global__ void k_tr(const float* __restrict__ z) {
    __shared__ float s[CC][33];
    int b = blockIdx.x >> 5, h = blockIdx.x & 31;
    int w = threadIdx.x & 31, t8 = threadIdx.x >> 5;
    const float* zp = z + ((long long)(b * CC) * HH + h) * WW + w;
#pragma unroll
    for (int i = 0; i < 32; i++) {
        int c = t8 * 32 + i;
        s[c][w] = zp[(long long)c * HH * WW];
    }
    __syncthreads();
    float* out = g_zp + (long long)b * ZP_BATCH + h * (WW * CC);
#pragma unroll
    for (int i = 0; i < 32; i++) {
        int f = threadIdx.x + i * 256;
        int c = f & 255, ww = f >> 8;
        out[f] = s[c][ww];
    }
    // A(n, 8h+c') = flat[(8h+c')*1024 + n] = s[n & 255][c'*4 + (n>>8)]
    int tid = threadIdx.x;
#pragma unroll
    for (int i = 0; i < 4; i++) {
        int n = i * 256 + tid;
        __align__(16) __half hh[8];
#pragma unroll
        for (int cp = 0; cp < 8; cp++)
            hh[cp] = __float2half_rn(s[tid][cp * 4 + i]);
        long long off = ((long long)b * NN + n) * CC + h * 8;
        *(uint4*)&g_zh[off] = *(uint4*)hh;
    }
}

// ---------- kernel 3: z2[b][n] over the REINTERPRETED [256,1024] view ----------
__global__ void k_z2() {
    int b = blockIdx.x >> 2;
    int n = (blockIdx.x & 3) * 256 + threadIdx.x;
    const float* base = g_zp + (long long)b * ZP_BATCH + n;
    float s = 0.f;
#pragma unroll 8
    for (int i = 0; i < CC; i++) { float v = base[i * NN]; s = fmaf(v, v, s); }
    g_z2[b * NN + n] = s;
}

// ---------- kernel 4: hi-only fp16 mma screening + certified top-2 ----------
// Warp (wr = w>>3, wp = w&7): A rows [16wp,16wp+16), codes [wr*64, wr*64+64) per slab.
__global__ void __launch_bounds__(512, 1) k_mma(float* __restrict__ dout, int out_size) {
    extern __shared__ uint32_t smu[];
    float* e2s = (float*)(smu + OFF_E2);
    uint32_t sb = smem_u32(smu);

    int tid = threadIdx.x;
    int w = tid >> 5, lane = tid & 31;
    int g = lane >> 2, t = lane & 3;
    int wr = w >> 3, wp = w & 7;
    int b = blockIdx.x >> 3;
    int n0 = (blockIdx.x & 7) * 128;

    // ---- A panel copy (hi only, padded rows) ----
    {
        const __half* zh = g_zh + ((long long)b * NN + n0) * CC;
#pragma unroll
        for (int i = 0; i < 8; i++) {
            int unit = tid + 512 * i;
            int r = unit >> 5, j = unit & 31;
            *(uint4*)(smu + OFF_AH + r * 132 + j * 4) = *(const uint4*)(zh + r * 256 + j * 8);
        }
    }
    for (int i = tid; i < KK; i += 512) e2s[i] = g_e2[i];

    // ---- E staging roles: thread = (k-row, 16B quarter) ----
    int ekr = tid >> 2, eq = tid & 3;
    // preload chunks 0 and 1 into ring bufs 0,1
    {
        uint4 c0 = *(const uint4*)(g_eh + ekr * 256 + eq * 8);
        uint4 c1 = *(const uint4*)(g_eh + ekr * 256 + 32 + eq * 8);
        *(uint4*)(smu + OFF_EB + ekr * 20 + eq * 4) = c0;
        *(uint4*)(smu + OFF_EB + EB_SEG + ekr * 20 + eq * 4) = c1;
    }

    // ---- frag addresses (bytes) ----
    uint32_t a_row = (uint32_t)((wp * 16 + (lane & 15)) * 132 + (lane >> 4) * 4);
    uint32_t aaddr = sb + (OFF_AH + a_row) * 4;
    uint32_t b_row = (uint32_t)((wr * 64 + (lane & 7) + ((lane >> 4) & 1) * 8) * 20
                                + ((lane >> 3) & 1) * 4);

    int p0 = wp * 16 + g, p1 = p0 + 8;
    float z2a = g_z2[b * NN + n0 + p0];
    float z2b = g_z2[b * NN + n0 + p1];
    float v1a = 3.4e38f, v2a = 3.4e38f, v1b = 3.4e38f, v2b = 3.4e38f;
    int   k1a = 0, k1b = 0;
    __syncthreads();

    float acc[8][4];
    uint4 pre;

    for (int q = 0; q < 64; q++) {             // chunk: k-slab q>>3, c-range (q&7)*32
        int ch = q & 7;
        if (ch == 0) {
#pragma unroll
            for (int f = 0; f < 8; f++)
#pragma unroll
                for (int j = 0; j < 4; j++) acc[f][j] = 0.f;
        }
        if (q + 2 < 64) {                       // prefetch distance 2
            int nk0 = ((q + 2) >> 3) * 128, nc0 = ((q + 2) & 7) * 32;
            pre = *(const uint4*)(g_eh + (nk0 + ekr) * 256 + nc0 + eq * 8);
        }

        uint32_t ebase = sb + (uint32_t)((OFF_EB + (q & 3) * EB_SEG) * 4);
#pragma unroll
        for (int s = 0; s < 2; s++) {
            uint32_t ah[4];
            ldsm4(ah, aaddr + ch * 64 + s * 32);
#pragma unroll
            for (int nfp = 0; nfp < 4; nfp++) {
                uint32_t baddr = ebase + (b_row + nfp * 320) * 4 + s * 32;
                uint32_t bh[4];
                ldsm4(bh, baddr);
                mma_f16(acc[nfp * 2], ah, bh[0], bh[1]);
                mma_f16(acc[nfp * 2 + 1], ah, bh[2], bh[3]);
            }
        }

        if (ch == 7) {                          // slab done: fold top-2
            int k0 = (q >> 3) * 128;
#pragma unroll
            for (int nf = 0; nf < 8; nf++) {
                int ka = k0 + wr * 64 + nf * 8 + 2 * t;
                float e2a = e2s[ka], e2b = e2s[ka + 1];
                float d0 = (e2a + z2a) - 2.0f * acc[nf][0];
                float d1 = (e2b + z2a) - 2.0f * acc[nf][1];
                float d2 = (e2a + z2b) - 2.0f * acc[nf][2];
                float d3 = (e2b + z2b) - 2.0f * acc[nf][3];
                top2_upd(v1a, k1a, v2a, d0, ka);
                top2_upd(v1a, k1a, v2a, d1, ka + 1);
                top2_upd(v1b, k1b, v2b, d2, ka);
                top2_upd(v1b, k1b, v2b, d3, ka + 1);
            }
        }

        if (q + 2 < 64) {                       // store prefetched chunk into ring
            *(uint4*)(smu + OFF_EB + (uint32_t)((q + 2) & 3) * EB_SEG + ekr * 20 + eq * 4) = pre;
        }
        if (q & 1) __syncthreads();             // barrier every 2 chunks (dist-2 safe)
    }

    // reduce over the 4 lanes of each group
#pragma unroll
    for (int off = 1; off <= 2; off <<= 1) {
        float V1 = __shfl_xor_sync(0xFFFFFFFFu, v1a, off);
        int   K1 = __shfl_xor_sync(0xFFFFFFFFu, k1a, off);
        float V2 = __shfl_xor_sync(0xFFFFFFFFu, v2a, off);
        top2_merge(v1a, k1a, v2a, V1, K1, V2);
        V1 = __shfl_xor_sync(0xFFFFFFFFu, v1b, off);
        K1 = __shfl_xor_sync(0xFFFFFFFFu, k1b, off);
        V2 = __shfl_xor_sync(0xFFFFFFFFu, v2b, off);
        top2_merge(v1b, k1b, v2b, V1, K1, V2);
    }

    // cross-wr combine via smem (A panel dead; reuse)
    float* rv1 = (float*)smu;             // [2][128]
    int*   rk1 = (int*)(smu + 256);
    float* rv2 = (float*)(smu + 512);
    __syncthreads();
    if (t == 0) {
        rv1[wr * 128 + p0] = v1a; rk1[wr * 128 + p0] = k1a; rv2[wr * 128 + p0] = v2a;
        rv1[wr * 128 + p1] = v1b; rk1[wr * 128 + p1] = k1b; rv2[wr * 128 + p1] = v2b;
    }
    __syncthreads();
    if (tid < 128) {
        float v1 = rv1[tid]; int k1 = rk1[tid]; float v2 = rv2[tid];
        top2_merge(v1, k1, v2, rv1[128 + tid], rk1[128 + tid], rv2[128 + tid]);
        int n = n0 + tid;
        int id = b * NN + n;
        g_idx[id] = k1;
        long long off = (long long)ZQ_SIZE + id;
        if (off < (long long)out_size) dout[off] = (float)k1;
        // certified margin: E = 2^-9 * sqrt(z2) * smax + 1e-4
        float smax = __uint_as_float(g_smax_bits);
        float Eb = 0.001953125f * sqrtf(g_z2[id]) * smax + 1.0e-4f;
        if (v2 < v1 + 2.0f * Eb) {
            int pos = atomicAdd(&g_cnt, 1);
            g_list[pos] = id;
        }
    }
}

// ---------- kernel 5: exact fp32 rescore of flagged pixels ----------
// 16 pixels per block; E tiled 16 k-rows at a time through smem.
__global__ void __launch_bounds__(256) k_rescore(const float* __restrict__ E,
                                                 float* __restrict__ dout, int out_size) {
    __shared__ float zcol[16][260];
    __shared__ float erow[16][260];
    __shared__ float z2s[16];
    __shared__ int   ids[16];
    __shared__ float sval[16][17];
    __shared__ int   sidx[16][17];

    int cnt = g_cnt;
    int base = blockIdx.x * 16;
    if (base >= cnt) return;
    int npx = min(16, cnt - base);
    int tid = threadIdx.x;
    int px = tid >> 4, kk = tid & 15;

    if (tid < 16) {
        int v = (tid < npx) ? g_list[base + tid] : g_list[base];
        ids[tid] = v;
        z2s[tid] = g_z2[v];
    }
    __syncthreads();
    // stage z view-columns: thread (px, kk) loads c = kk*16 + j
    {
        int id = ids[px];
        int bb = id >> 10, nn = id & 1023;
        const float* zb = g_zp + (long long)bb * ZP_BATCH + nn;
#pragma unroll 4
        for (int j = 0; j < 16; j++) {
            int c = kk * 16 + j;
            zcol[px][c] = zb[c * 1024];
        }
    }

    float bv = 3.4e38f;
    int bk = 0;
    for (int kt = 0; kt < 64; kt++) {
        __syncthreads();
        {   // stage E tile rows kt*16+px, 16 floats at kk*16
            const float* er = E + (kt * 16 + px) * CC + kk * 16;
            *(float4*)&erow[px][kk * 16]      = *(const float4*)(er);
            *(float4*)&erow[px][kk * 16 + 4]  = *(const float4*)(er + 4);
            *(float4*)&erow[px][kk * 16 + 8]  = *(const float4*)(er + 8);
            *(float4*)&erow[px][kk * 16 + 12] = *(const float4*)(er + 12);
        }
        __syncthreads();
        float dot = 0.f;
#pragma unroll 8
        for (int c4 = 0; c4 < 64; c4++) {
            float4 zv = *(const float4*)&zcol[px][c4 * 4];
            float4 ev = *(const float4*)&erow[kk][c4 * 4];
            dot = fmaf(zv.x, ev.x, dot);
            dot = fmaf(zv.y, ev.y, dot);
            dot = fmaf(zv.z, ev.z, dot);
            dot = fmaf(zv.w, ev.w, dot);
        }
        int k = kt * 16 + kk;
        float dist = (g_e2[k] + z2s[px]) - 2.0f * dot;
        if (dist < bv || (dist == bv && k < bk)) { bv = dist; bk = k; }
    }
    sval[px][kk] = bv;
    sidx[px][kk] = bk;
    __syncthreads();
    if (kk == 0 && px < npx) {
        float v = sval[px][0]; int k = sidx[px][0];
#pragma unroll
        for (int i = 1; i < 16; i++) {
            float vv = sval[px][i]; int k2 = sidx[px][i];
            if (vv < v || (vv == v && k2 < k)) { v = vv; k = k2; }
        }
        int id = ids[px];
        g_idx[id] = k;
        long long off = (long long)ZQ_SIZE + id;
        if (off < (long long)out_size) dout[off] = (float)k;
    }
}

// ---------- kernel 6: gather z_q (STE-exact), loss partials ----------
__global__ void k_gather(const float* __restrict__ z, const float* __restrict__ E,
                         float* __restrict__ dout) {
    __shared__ float srow[32 * 257];
    __shared__ int   skid[32];
    __shared__ float sw[8];
    int b = blockIdx.x >> 5, h = blockIdx.x & 31;
    int tid = threadIdx.x;
    int warp = tid >> 5, lane = tid & 31;

    if (tid < 32) skid[tid] = g_idx[b * NN + h * WW + tid];
    __syncthreads();

#pragma unroll
    for (int r2 = 0; r2 < 4; r2++) {
        int r = warp * 4 + r2;
        const float* er = E + skid[r] * CC;
#pragma unroll
        for (int i = 0; i < 8; i++)
            srow[r * 257 + lane + 32 * i] = er[lane + 32 * i];
    }
    __syncthreads();

    int w = lane;
    float local = 0.f;
#pragma unroll 4
    for (int s = 0; s < 32; s++) {
        int c = warp * 32 + s;
        long long zoff = ((long long)(b * CC + c) * HH + h) * WW + w;
        float zv = z[zoff];
        float eq = srow[w * 257 + c];
        float d = eq - zv;
        local = fmaf(d, d, local);
        dout[zoff] = zv + (eq - zv);   // exact straight-through arithmetic
    }
#pragma unroll
    for (int o = 16; o; o >>= 1) local += __shfl_xor_sync(0xFFFFFFFFu, local, o);
    if (lane == 0) sw[warp] = local;
    __syncthreads();
    if (tid == 0) {
        float s2 = 0.f;
#pragma unroll
        for (int i = 0; i < 8; i++) s2 += sw[i];
        g_losspart[blockIdx.x] = s2;
    }
}

// ---------- kernel 7: deterministic loss finalize ----------
__global__ void k_final(float* __restrict__ dout, int out_size) {
    __shared__ float smf[256];
    float s = 0.f;
    for (int i = threadIdx.x; i < 1024; i += 256) s += g_losspart[i];
    smf[threadIdx.x] = s;
    __syncthreads();
    if (threadIdx.x == 0) {
        float t = 0.f;
        for (int i = 0; i < 256; i++) t += smf[i];
        float m = t / 8388608.0f;
        float loss = m + 0.25f * m;
        long long off = (long long)ZQ_SIZE + IDX_SIZE;
        if (off < (long long)out_size) dout[off] = loss;
    }
}

extern "C" void kernel_launch(void* const* d_in, const int* in_sizes, int n_in,
                              void* d_out, int out_size) {
    const float* z = (const float*)d_in[0];
    const float* E = (const float*)d_in[1];
    float* out = (float*)d_out;

    cudaFuncSetAttribute(k_mma, cudaFuncAttributeMaxDynamicSharedMemorySize, SMEM_MMA_BYTES);

    k_init<<<1, 1>>>();
    k_e2<<<128, 256>>>(E);
    k_tr<<<1024, 256>>>(z);
    k_z2<<<128, 256>>>();
    k_mma<<<256, 512, SMEM_MMA_BYTES>>>(out, out_size);
    k_rescore<<<2048, 256>>>(E, out, out_size);
    if (out_size >= ZQ_SIZE) k_gather<<<1024, 256>>>(z, E, out);
    k_final<<<1, 256>>>(out, out_size);
}

// round 14
// speedup vs baseline: 2.7408x; 2.7408x over previous
#include <cuda_runtime.h>
#include <cuda_fp16.h>
#include <cstdint>

// Problem constants
#define BB 32
#define CC 256
#define HH 32
#define WW 32
#define KK 1024
#define NN 1024                      // H*W
#define ZP_BATCH (CC * NN)           // 262144 floats per batch
#define ZQ_SIZE (BB * CC * HH * WW)  // 8388608
#define IDX_SIZE (BB * NN)           // 32768

// ---------------- k_mma smem layout (u32 units) ----------------
// A hi [128 n][132] @ 0, A lo @ 16896
// E [4 wr][2 buf][hi/lo][32 k][20] @ 33792  (10240 u32)
// e2s float[1024] @ 44032
#define OFF_AH 0
#define OFF_AL 16896
#define AL_B   67584                  // OFF_AL * 4 bytes
#define MT_B   8448                   // 16 rows * 132 u32 * 4 B
#define OFF_EB 33792
#define EWR_SEG 2560                  // per wr group (u32)
#define EBUF_SEG 1280                 // per buffer
#define ESPL_SEG 640                  // per split
#define OFF_E2 44032
#define SMEM_U32 45056
#define SMEM_MMA_BYTES (SMEM_U32 * 4)   // 180224

#define INV2048 4.8828125e-4f

// Device scratch (allocation-free rule: __device__ globals)
__device__ float g_zp[BB * ZP_BATCH];   // contiguous [b][h][w][c] image of z_p
__device__ float g_e2[KK];
__device__ float g_z2[BB * NN];         // view-column norms
__device__ int   g_idx[BB * NN];
__device__ float g_losspart[1024];
// pre-split fp16 operands
__device__ __align__(16) __half g_eh[KK * CC];          // E hi halves [k][c]
__device__ __align__(16) __half g_el[KK * CC];          // E lo halves
__device__ __align__(16) __half g_zh[BB * NN * CC];     // A hi halves [b][n][c] (view rows)
__device__ __align__(16) __half g_zl[BB * NN * CC];     // A lo halves

// ---------- helpers ----------
__device__ __forceinline__ __half lo_split(float x, __half h) {
    return __float2half_rn((x - __half2float(h)) * 2048.0f);
}
__device__ __forceinline__ uint32_t smem_u32(const void* p) {
    uint32_t a;
    asm("{ .reg .u64 t; cvta.to.shared.u64 t, %1; cvt.u32.u64 %0, t; }" : "=r"(a) : "l"(p));
    return a;
}
__device__ __forceinline__ void ldsm4(uint32_t* r, uint32_t addr) {
    asm volatile("ldmatrix.sync.aligned.m8n8.x4.shared.b16 {%0,%1,%2,%3}, [%4];"
                 : "=r"(r[0]), "=r"(r[1]), "=r"(r[2]), "=r"(r[3]) : "r"(addr));
}
__device__ __forceinline__ void mma_f16(float* d, const uint32_t* a,
                                        uint32_t b0, uint32_t b1) {
    asm volatile(
        "mma.sync.aligned.m16n8k16.row.col.f32.f16.f16.f32 "
        "{%0,%1,%2,%3}, {%4,%5,%6,%7}, {%8,%9}, {%0,%1,%2,%3};"
        : "+f"(d[0]), "+f"(d[1]), "+f"(d[2]), "+f"(d[3])
        : "r"(a[0]), "r"(a[1]), "r"(a[2]), "r"(a[3]), "r"(b0), "r"(b1));
}

// ---------- kernel 1: e2[k] + pre-split E halves ----------
__global__ void k_e2(const float* __restrict__ E) {
    int warp = threadIdx.x >> 5, lane = threadIdx.x & 31;
    int k = blockIdx.x * 8 + warp;
    const float* row = E + k * CC;
    float v[8];
    float s = 0.f;
#pragma unroll
    for (int i = 0; i < 8; i++) { v[i] = row[lane + 32 * i]; s = fmaf(v[i], v[i], s); }
#pragma unroll
    for (int o = 16; o; o >>= 1) s += __shfl_xor_sync(0xFFFFFFFFu, s, o);
    if (lane == 0) g_e2[k] = s;
#pragma unroll
    for (int i = 0; i < 8; i++) {
        int c = lane + 32 * i;
        __half hv = __float2half_rn(v[i]);
        g_eh[k * CC + c] = hv;
        g_el[k * CC + c] = lo_split(v[i], hv);
    }
}

// ---------- kernel 2: transpose z -> g_zp, and emit A-row halves ----------
__global__ void k_tr(const float* __restrict__ z) {
    __shared__ float s[CC][33];
    int b = blockIdx.x >> 5, h = blockIdx.x & 31;
    int w = threadIdx.x & 31, t8 = threadIdx.x >> 5;
    const float* zp = z + ((long long)(b * CC) * HH + h) * WW + w;
#pragma unroll
    for (int i = 0; i < 32; i++) {
        int c = t8 * 32 + i;
        s[c][w] = zp[(long long)c * HH * WW];
    }
    __syncthreads();
    float* out = g_zp + (long long)b * ZP_BATCH + h * (WW * CC);
#pragma unroll
    for (int i = 0; i < 32; i++) {
        int f = threadIdx.x + i * 256;
        int c = f & 255, ww = f >> 8;
        out[f] = s[c][ww];
    }
    // A(n, 8h+c') = flat[(8h+c')*1024 + n] = s[n & 255][c'*4 + (n>>8)]
    int tid = threadIdx.x;
#pragma unroll
    for (int i = 0; i < 4; i++) {
        int n = i * 256 + tid;
        __align__(16) __half hh[8], ll[8];
#pragma unroll
        for (int cp = 0; cp < 8; cp++) {
            float v = s[tid][cp * 4 + i];
            __half hv = __float2half_rn(v);
            hh[cp] = hv;
            ll[cp] = lo_split(v, hv);
        }
        long long off = ((long long)b * NN + n) * CC + h * 8;
        *(uint4*)&g_zh[off] = *(uint4*)hh;
        *(uint4*)&g_zl[off] = *(uint4*)ll;
    }
}

// ---------- kernel 3: z2[b][n] over the REINTERPRETED [256,1024] view ----------
__global__ void k_z2() {
    int b = blockIdx.x >> 2;
    int n = (blockIdx.x & 3) * 256 + threadIdx.x;
    const float* base = g_zp + (long long)b * ZP_BATCH + n;
    float s = 0.f;
#pragma unroll 8
    for (int i = 0; i < CC; i++) { float v = base[i * NN]; s = fmaf(v, v, s); }
    g_z2[b * NN + n] = s;
}

// ---------- kernel 4: fp16 2-split mma.sync + ldmatrix + argmin ----------
// 512 thr. Warp w: wp = w&3 (rows [wp*32, wp*32+32)), wr = w>>2 (codes [wr*32,+32) per slab).
// Each wr-group (4 warps = 128 contiguous threads, one per SMSP) owns its E rows
// and syncs on named barrier wr+1 -> independent pipelines overlap LDSM with HMMA.
__global__ void __launch_bounds__(512, 1) k_mma(float* __restrict__ dout, int out_size) {
    extern __shared__ uint32_t smu[];
    float* e2s = (float*)(smu + OFF_E2);
    uint32_t sb = smem_u32(smu);

    int tid = threadIdx.x;
    int w = tid >> 5, lane = tid & 31;
    int g = lane >> 2, t = lane & 3;
    int wr = w >> 2, wp = w & 3;
    int b = blockIdx.x >> 3;
    int n0 = (blockIdx.x & 7) * 128;

    // ---- A panel copy (128 rows, pre-split halves, padded rows) ----
    {
        const __half* zh = g_zh + ((long long)b * NN + n0) * CC;
        const __half* zl = g_zl + ((long long)b * NN + n0) * CC;
#pragma unroll
        for (int i = 0; i < 8; i++) {
            int unit = tid + 512 * i;
            int r = unit >> 5, j = unit & 31;
            *(uint4*)(smu + OFF_AH + r * 132 + j * 4) = *(const uint4*)(zh + r * 256 + j * 8);
            *(uint4*)(smu + OFF_AL + r * 132 + j * 4) = *(const uint4*)(zl + r * 256 + j * 8);
        }
    }
    for (int i = tid; i < KK; i += 512) e2s[i] = g_e2[i];

    // ---- E staging roles (group-local): tid_g in [0,128) ----
    int tid_g = tid & 127;
    int ekr = tid_g >> 2, eq = tid_g & 3;       // row 0..31 within group's section, 16B quarter
    // stage chunk 0 into buf 0 (group rows of slab 0)
    {
        const __half* eh = g_eh + (wr * 32 + ekr) * 256 + eq * 8;
        const __half* el = g_el + (wr * 32 + ekr) * 256 + eq * 8;
        uint32_t* dst = smu + OFF_EB + wr * EWR_SEG + ekr * 20 + eq * 4;
        *(uint4*)dst = *(const uint4*)eh;
        *(uint4*)(dst + ESPL_SEG) = *(const uint4*)el;
    }

    // ---- frag addresses (bytes) ----
    uint32_t a_row = (uint32_t)((wp * 32 + (lane & 15)) * 132 + (lane >> 4) * 4);
    uint32_t aaddr = sb + a_row * 4;
    uint32_t b_row = (uint32_t)(((lane & 7) + ((lane >> 4) & 1) * 8) * 20
                                + ((lane >> 3) & 1) * 4);

    // per-thread argmin state: rows (mt in {0,1}) x (g, g+8)
    float z2r[4], bv[4];
    int   bk[4];
#pragma unroll
    for (int mt = 0; mt < 2; mt++)
#pragma unroll
        for (int r8 = 0; r8 < 2; r8++) {
            z2r[mt * 2 + r8] = g_z2[b * NN + n0 + wp * 32 + mt * 16 + g + r8 * 8];
            bv[mt * 2 + r8] = 3.4e38f; bk[mt * 2 + r8] = 0;
        }
    __syncthreads();

    float acc_hh[8][4], acc_lo[8][4];          // f = mt*4 + nf
    uint4 ph, pl;

    for (int q = 0; q < 64; q++) {             // chunk: k-slab q>>3, c-range (q&7)*32
        int buf = q & 1, ch = q & 7;
        if (ch == 0) {
#pragma unroll
            for (int f = 0; f < 8; f++)
#pragma unroll
                for (int j = 0; j < 4; j++) { acc_hh[f][j] = 0.f; acc_lo[f][j] = 0.f; }
        }
        if (q + 1 < 64) {                      // prefetch next chunk (group rows)
            int nk0 = ((q + 1) >> 3) * 128, nc0 = ((q + 1) & 7) * 32;
            const __half* eh = g_eh + (nk0 + wr * 32 + ekr) * 256 + nc0 + eq * 8;
            const __half* el = g_el + (nk0 + wr * 32 + ekr) * 256 + nc0 + eq * 8;
            ph = *(const uint4*)eh;
            pl = *(const uint4*)el;
        }

        uint32_t ebase = sb + (uint32_t)((OFF_EB + wr * EWR_SEG + buf * EBUF_SEG) * 4);
#pragma unroll
        for (int s = 0; s < 2; s++) {
            uint32_t co = (uint32_t)(ch * 64 + s * 32);
            uint32_t ah0[4], ah1[4], al0[4], al1[4];
            ldsm4(ah0, aaddr + co);
            ldsm4(ah1, aaddr + MT_B + co);
            ldsm4(al0, aaddr + AL_B + co);
            ldsm4(al1, aaddr + AL_B + MT_B + co);
#pragma unroll
            for (int np = 0; np < 2; np++) {
                uint32_t baddr = ebase + (b_row + np * 320) * 4 + s * 32;
                uint32_t bh[4], bl[4];
                ldsm4(bh, baddr);
                ldsm4(bl, baddr + ESPL_SEG * 4);
                int nf0 = np * 2, nf1 = nf0 + 1;
                // mt 0
                mma_f16(acc_hh[nf0], ah0, bh[0], bh[1]);
                mma_f16(acc_hh[nf1], ah0, bh[2], bh[3]);
                mma_f16(acc_lo[nf0], ah0, bl[0], bl[1]);
                mma_f16(acc_lo[nf1], ah0, bl[2], bl[3]);
                mma_f16(acc_lo[nf0], al0, bh[0], bh[1]);
                mma_f16(acc_lo[nf1], al0, bh[2], bh[3]);
                // mt 1
                mma_f16(acc_hh[4 + nf0], ah1, bh[0], bh[1]);
                mma_f16(acc_hh[4 + nf1], ah1, bh[2], bh[3]);
                mma_f16(acc_lo[4 + nf0], ah1, bl[0], bl[1]);
                mma_f16(acc_lo[4 + nf1], ah1, bl[2], bl[3]);
                mma_f16(acc_lo[4 + nf0], al1, bh[0], bh[1]);
                mma_f16(acc_lo[4 + nf1], al1, bh[2], bh[3]);
            }
        }

        if (ch == 7) {                          // k-slab done: fold argmin
            int k0 = (q >> 3) * 128;
#pragma unroll
            for (int mt = 0; mt < 2; mt++)
#pragma unroll
            for (int nf = 0; nf < 4; nf++) {
                int f = mt * 4 + nf;
                int ka = k0 + wr * 32 + nf * 8 + 2 * t;
                float e2a = e2s[ka], e2b = e2s[ka + 1];
                float dot0 = fmaf(acc_lo[f][0], INV2048, acc_hh[f][0]);
                float dot1 = fmaf(acc_lo[f][1], INV2048, acc_hh[f][1]);
                float dot2 = fmaf(acc_lo[f][2], INV2048, acc_hh[f][2]);
                float dot3 = fmaf(acc_lo[f][3], INV2048, acc_hh[f][3]);
                int ia = mt * 2, ib = mt * 2 + 1;
                float d0 = (e2a + z2r[ia]) - 2.0f * dot0;
                float d1 = (e2b + z2r[ia]) - 2.0f * dot1;
                float d2 = (e2a + z2r[ib]) - 2.0f * dot2;
                float d3 = (e2b + z2r[ib]) - 2.0f * dot3;
                if (d0 < bv[ia] || (d0 == bv[ia] && ka     < bk[ia])) { bv[ia] = d0; bk[ia] = ka; }
                if (d1 < bv[ia] || (d1 == bv[ia] && ka + 1 < bk[ia])) { bv[ia] = d1; bk[ia] = ka + 1; }
                if (d2 < bv[ib] || (d2 == bv[ib] && ka     < bk[ib])) { bv[ib] = d2; bk[ib] = ka; }
                if (d3 < bv[ib] || (d3 == bv[ib] && ka + 1 < bk[ib])) { bv[ib] = d3; bk[ib] = ka + 1; }
            }
        }

        if (q + 1 < 64) {                      // store prefetched chunk into other buffer
            uint32_t* dst = smu + OFF_EB + wr * EWR_SEG + (uint32_t)(buf ^ 1) * EBUF_SEG
                          + ekr * 20 + eq * 4;
            *(uint4*)dst = ph;
            *(uint4*)(dst + ESPL_SEG) = pl;
        }
        // group-local barrier: 4 warps (128 threads) of this wr-group only
        asm volatile("bar.sync %0, 128;" :: "r"(wr + 1) : "memory");
    }

    // reduce over the 4 lanes of each group (lexicographic, first-k preference)
#pragma unroll
    for (int i = 0; i < 4; i++) {
#pragma unroll
        for (int off = 1; off <= 2; off <<= 1) {
            float ov = __shfl_xor_sync(0xFFFFFFFFu, bv[i], off);
            int   ok = __shfl_xor_sync(0xFFFFFFFFu, bk[i], off);
            if (ov < bv[i] || (ov == bv[i] && ok < bk[i])) { bv[i] = ov; bk[i] = ok; }
        }
    }

    // cross-wr combine via smem (A panel dead; reuse)
    float* rval = (float*)smu;            // [4 wr][128 rows]
    int*   ridx = (int*)(smu + 512);      // [4 wr][128 rows]
    __syncthreads();
    if (t == 0) {
#pragma unroll
        for (int mt = 0; mt < 2; mt++)
#pragma unroll
            for (int r8 = 0; r8 < 2; r8++) {
                int row = wp * 32 + mt * 16 + g + r8 * 8;
                rval[wr * 128 + row] = bv[mt * 2 + r8];
                ridx[wr * 128 + row] = bk[mt * 2 + r8];
            }
    }
    __syncthreads();
    if (tid < 128) {
        float bvv = rval[tid];
        int   bkk = ridx[tid];
#pragma unroll
        for (int r = 1; r < 4; r++) {
            float v = rval[r * 128 + tid];
            int   k2 = ridx[r * 128 + tid];
            if (v < bvv || (v == bvv && k2 < bkk)) { bvv = v; bkk = k2; }
        }
        int n = n0 + tid;
        g_idx[b * NN + n] = bkk;
        long long off = (long long)ZQ_SIZE + b * NN + n;
        if (off < (long long)out_size) dout[off] = (float)bkk;
    }
}

// ---------- kernel 5: gather z_q (STE-exact), loss partials ----------
__global__ void k_gather(const float* __restrict__ z, const float* __restrict__ E,
                         float* __restrict__ dout) {
    __shared__ float srow[32 * 257];
    __shared__ int   skid[32];
    __shared__ float sw[8];
    int b = blockIdx.x >> 5, h = blockIdx.x & 31;
    int tid = threadIdx.x;
    int warp = tid >> 5, lane = tid & 31;

    if (tid < 32) skid[tid] = g_idx[b * NN + h * WW + tid];
    __syncthreads();

#pragma unroll
    for (int r2 = 0; r2 < 4; r2++) {
        int r = warp * 4 + r2;
        const float* er = E + skid[r] * CC;
#pragma unroll
        for (int i = 0; i < 8; i++)
            srow[r * 257 + lane + 32 * i] = er[lane + 32 * i];
    }
    __syncthreads();

    int w = lane;
    float local = 0.f;
#pragma unroll 4
    for (int s = 0; s < 32; s++) {
        int c = warp * 32 + s;
        long long zoff = ((long long)(b * CC + c) * HH + h) * WW + w;
        float zv = z[zoff];
        float eq = srow[w * 257 + c];
        float d = eq - zv;
        local = fmaf(d, d, local);
        dout[zoff] = zv + (eq - zv);   // exact straight-through arithmetic
    }
#pragma unroll
    for (int o = 16; o; o >>= 1) local += __shfl_xor_sync(0xFFFFFFFFu, local, o);
    if (lane == 0) sw[warp] = local;
    __syncthreads();
    if (tid == 0) {
        float s2 = 0.f;
#pragma unroll
        for (int i = 0; i < 8; i++) s2 += sw[i];
        g_losspart[blockIdx.x] = s2;
    }
}

// ---------- kernel 6: deterministic loss finalize ----------
__global__ void k_final(float* __restrict__ dout, int out_size) {
    __shared__ float smf[256];
    float s = 0.f;
    for (int i = threadIdx.x; i < 1024; i += 256) s += g_losspart[i];
    smf[threadIdx.x] = s;
    __syncthreads();
    if (threadIdx.x == 0) {
        float t = 0.f;
        for (int i = 0; i < 256; i++) t += smf[i];
        float m = t / 8388608.0f;
        float loss = m + 0.25f * m;
        long long off = (long long)ZQ_SIZE + IDX_SIZE;
        if (off < (long long)out_size) dout[off] = loss;
    }
}

extern "C" void kernel_launch(void* const* d_in, const int* in_sizes, int n_in,
                              void* d_out, int out_size) {
    const float* z = (const float*)d_in[0];
    const float* E = (const float*)d_in[1];
    float* out = (float*)d_out;

    cudaFuncSetAttribute(k_mma, cudaFuncAttributeMaxDynamicSharedMemorySize, SMEM_MMA_BYTES);

    k_e2<<<128, 256>>>(E);
    k_tr<<<1024, 256>>>(z);
    k_z2<<<128, 256>>>();
    k_mma<<<256, 512, SMEM_MMA_BYTES>>>(out, out_size);
    if (out_size >= ZQ_SIZE) k_gather<<<1024, 256>>>(z, E, out);
    k_final<<<1, 256>>>(out, out_size);
}